// round 3
// baseline (speedup 1.0000x reference)
#include <cuda_runtime.h>
#include <cuda_bf16.h>

// BalancedBCE fused single-kernel:
//   per-block partials of {S_pos[b], S_neg[b], pos_count[b]} -> g_part
//   last-arriving block (fence + atomic ticket) reduces all partials and
//   writes the scalar loss. Ticket is reset -> deterministic across graph
//   replays; the float reduction order is fixed, so the result is bitwise
//   stable.

#define BATCH   64
#define BPB     32      // blocks per batch sample
#define THREADS 256
#define NBLOCKS (BATCH * BPB)   // 2048

// layout: g_part[blk*192 + qty*64 + b], qty: 0=S_pos 1=S_neg 2=count
// -> final-reduce loads are 64-wide coalesced per (blk, qty).
__device__ float g_part[NBLOCKS * 3];
__device__ unsigned int g_ticket = 0;

__device__ __forceinline__ void block_reduce3(float& a, float& b, float& c) {
    #pragma unroll
    for (int off = 16; off > 0; off >>= 1) {
        a += __shfl_down_sync(0xFFFFFFFFu, a, off);
        b += __shfl_down_sync(0xFFFFFFFFu, b, off);
        c += __shfl_down_sync(0xFFFFFFFFu, c, off);
    }
    __shared__ float sa[THREADS / 32], sb[THREADS / 32], sc[THREADS / 32];
    int lane = threadIdx.x & 31;
    int warp = threadIdx.x >> 5;
    if (lane == 0) { sa[warp] = a; sb[warp] = b; sc[warp] = c; }
    __syncthreads();
    if (warp == 0) {
        a = (lane < THREADS / 32) ? sa[lane] : 0.0f;
        b = (lane < THREADS / 32) ? sb[lane] : 0.0f;
        c = (lane < THREADS / 32) ? sc[lane] : 0.0f;
        #pragma unroll
        for (int off = (THREADS / 64); off > 0; off >>= 1) {
            a += __shfl_down_sync(0xFFFFFFFFu, a, off);
            b += __shfl_down_sync(0xFFFFFFFFu, b, off);
            c += __shfl_down_sync(0xFFFFFFFFu, c, off);
        }
    }
}

__global__ void __launch_bounds__(THREADS)
bce_fused_kernel(const float* __restrict__ x_all,
                 const float* __restrict__ t_all,
                 int n_per_sample,
                 float* __restrict__ out)
{
    const int b   = blockIdx.y;         // batch sample
    const int blk = blockIdx.x;         // block within sample

    const float4* __restrict__ x4 =
        reinterpret_cast<const float4*>(x_all + (size_t)b * n_per_sample);
    const float4* __restrict__ t4 =
        reinterpret_cast<const float4*>(t_all + (size_t)b * n_per_sample);
    const int n4 = n_per_sample >> 2;

    float sp = 0.0f, sn = 0.0f, cnt = 0.0f;

    for (int i = blk * THREADS + threadIdx.x; i < n4; i += BPB * THREADS) {
        float4 xv = x4[i];
        float4 tv = t4[i];
        float xs[4] = {xv.x, xv.y, xv.z, xv.w};
        float ts[4] = {tv.x, tv.y, tv.z, tv.w};
        #pragma unroll
        for (int k = 0; k < 4; k++) {
            float x = xs[k];
            float t = ts[k];                 // exactly 0.0 or 1.0
            float ax  = fabsf(x);
            float l   = __logf(1.0f + __expf(-ax));
            float bce = fmaxf(x, 0.0f) - x * t + l;
            sp  = fmaf(t, bce, sp);          // add bce when t==1
            sn  = fmaf(1.0f - t, bce, sn);   // add bce when t==0
            cnt += t;
        }
    }

    block_reduce3(sp, sn, cnt);

    __shared__ bool am_last;
    if (threadIdx.x == 0) {
        g_part[blk * 192 +   0 + b] = sp;
        g_part[blk * 192 +  64 + b] = sn;
        g_part[blk * 192 + 128 + b] = cnt;
        __threadfence();
        unsigned int t = atomicAdd(&g_ticket, 1u);
        am_last = (t == (unsigned)(NBLOCKS - 1));
    }
    __syncthreads();
    if (!am_last) return;

    // ---- last block: final reduction (64 active threads, one per sample) ----
    float wpos = 0.0f, wneg = 0.0f, cpos = 0.0f, cneg = 0.0f;
    if (threadIdx.x < BATCH) {
        const int bb = threadIdx.x;
        float Sp = 0.0f, Sn = 0.0f, C = 0.0f;
        #pragma unroll
        for (int j = 0; j < BPB; j++) {
            Sp += g_part[j * 192 +   0 + bb];
            Sn += g_part[j * 192 +  64 + bb];
            C  += g_part[j * 192 + 128 + bb];
        }
        float N     = (float)n_per_sample;
        float tmean = C / N;
        wpos = (1.0f - tmean) * Sp;    // beta_pos * S_pos
        wneg = tmean * Sn;             // beta_neg * S_neg
        cpos = C;
        cneg = N - C;
    }

    // reduce 4 values across the first 64 threads (2 warps)
    __shared__ float s0[2], s1[2], s2[2], s3[2];
    #pragma unroll
    for (int off = 16; off > 0; off >>= 1) {
        wpos += __shfl_down_sync(0xFFFFFFFFu, wpos, off);
        wneg += __shfl_down_sync(0xFFFFFFFFu, wneg, off);
        cpos += __shfl_down_sync(0xFFFFFFFFu, cpos, off);
        cneg += __shfl_down_sync(0xFFFFFFFFu, cneg, off);
    }
    int lane = threadIdx.x & 31;
    int warp = threadIdx.x >> 5;
    if (lane == 0 && warp < 2) { s0[warp] = wpos; s1[warp] = wneg; s2[warp] = cpos; s3[warp] = cneg; }
    __syncthreads();
    if (threadIdx.x == 0) {
        float WP = s0[0] + s0[1];
        float WN = s1[0] + s1[1];
        float CP = s2[0] + s2[1];
        float CN = s3[0] + s3[1];
        out[0] = WP / CP + WN / CN;
        g_ticket = 0;   // reset for next graph replay (deterministic)
    }
}

extern "C" void kernel_launch(void* const* d_in, const int* in_sizes, int n_in,
                              void* d_out, int out_size) {
    const float* x = (const float*)d_in[0];   // logits
    const float* t = (const float*)d_in[1];   // targets (0/1)
    float* out = (float*)d_out;

    const int total = in_sizes[0];
    const int n_per_sample = total / BATCH;   // 262144 for [64,1,512,512]

    dim3 grid(BPB, BATCH);
    bce_fused_kernel<<<grid, THREADS>>>(x, t, n_per_sample, out);
}